// round 1
// baseline (speedup 1.0000x reference)
#include <cuda_runtime.h>

// Problem constants
#define BB     8
#define HHDIM  32
#define WWDIM  32
#define LL     1024         // 32*32
#define CC     512
#define HEADS  4
#define KD     128
#define EMB    512
#define NREL   63           // 2*32 - 1

// Scratch (device globals: no allocations allowed)
__device__ float g_q [BB*LL*EMB];
__device__ float g_k [BB*LL*EMB];
__device__ float g_v [BB*LL*EMB];
__device__ float g_ao[BB*LL*EMB];
__device__ float g_rw[BB*HEADS*LL*NREL];
__device__ float g_rh[BB*HEADS*LL*NREL];

// ---------------------------------------------------------------------------
// GEMM: C[M=8192, 512] = A[8192,512] @ W[512,512] * scale
// BM=BN=128, BK=16, 256 threads, 8x8 micro-tile per thread.
// ---------------------------------------------------------------------------
__global__ __launch_bounds__(256) void gemm512(const float* __restrict__ A,
                                               const float* __restrict__ W,
                                               float* __restrict__ C,
                                               float scale)
{
    __shared__ float AsT[16 * 132];   // [k][m], padded
    __shared__ float Bs [16 * 128];   // [k][n]

    const int tid = threadIdx.x;
    const int tx  = tid & 15;
    const int ty  = tid >> 4;
    const int m0  = blockIdx.y * 128;
    const int n0  = blockIdx.x * 128;

    float acc[8][8];
#pragma unroll
    for (int i = 0; i < 8; i++)
#pragma unroll
        for (int j = 0; j < 8; j++) acc[i][j] = 0.f;

    for (int k0 = 0; k0 < 512; k0 += 16) {
#pragma unroll
        for (int p = 0; p < 2; p++) {
            int idx = tid + p * 256;              // 0..511
            // A tile: 128 x 16, one float4 along k per thread
            int m  = idx >> 2;
            int kq = idx & 3;
            float4 av = *(const float4*)&A[(size_t)(m0 + m) * 512 + k0 + kq * 4];
            AsT[(kq * 4 + 0) * 132 + m] = av.x;
            AsT[(kq * 4 + 1) * 132 + m] = av.y;
            AsT[(kq * 4 + 2) * 132 + m] = av.z;
            AsT[(kq * 4 + 3) * 132 + m] = av.w;
            // B tile: 16 x 128
            int kk = idx >> 5;
            int n4 = idx & 31;
            *(float4*)&Bs[kk * 128 + n4 * 4] =
                *(const float4*)&W[(size_t)(k0 + kk) * 512 + n0 + n4 * 4];
        }
        __syncthreads();

#pragma unroll
        for (int kk = 0; kk < 16; kk++) {
            float a[8], b[8];
            *(float4*)&a[0] = *(const float4*)&AsT[kk * 132 + ty * 8];
            *(float4*)&a[4] = *(const float4*)&AsT[kk * 132 + ty * 8 + 4];
            *(float4*)&b[0] = *(const float4*)&Bs [kk * 128 + tx * 8];
            *(float4*)&b[4] = *(const float4*)&Bs [kk * 128 + tx * 8 + 4];
#pragma unroll
            for (int i = 0; i < 8; i++)
#pragma unroll
                for (int j = 0; j < 8; j++) acc[i][j] += a[i] * b[j];
        }
        __syncthreads();
    }

#pragma unroll
    for (int i = 0; i < 8; i++) {
        float4 o0 = make_float4(acc[i][0]*scale, acc[i][1]*scale, acc[i][2]*scale, acc[i][3]*scale);
        float4 o1 = make_float4(acc[i][4]*scale, acc[i][5]*scale, acc[i][6]*scale, acc[i][7]*scale);
        size_t base = (size_t)(m0 + ty * 8 + i) * 512 + n0 + tx * 8;
        *(float4*)&C[base]     = o0;
        *(float4*)&C[base + 4] = o1;
    }
}

// ---------------------------------------------------------------------------
// Relative-position logits: RW[b,h,l,r] = sum_d q[b,l,h,d] * pos_w[d,r]
//                           RH[b,h,l,r] = sum_d q[b,l,h,d] * pos_h[d,r]
// CTA = 64 rows of the flattened (b*4+h)*1024 + l index space, 256 threads,
// 4x4 micro-tile (rows x r) per thread, both tables handled together.
// Dynamic smem: pos_w[128*64] + pos_h[128*64] + q[64*132] = 99,328 B.
// ---------------------------------------------------------------------------
#define RELPOS_SMEM ((8192 + 8192 + 64 * 132) * 4)

__global__ __launch_bounds__(256) void relpos(const float* __restrict__ q,
                                              const float* __restrict__ pew,
                                              const float* __restrict__ peh,
                                              float* __restrict__ rw,
                                              float* __restrict__ rh)
{
    extern __shared__ float sm[];
    float* pw = sm;               // [128][64] (col 63 zero-padded)
    float* ph = sm + 8192;        // [128][64]
    float* qs = sm + 16384;       // [64][132]

    const int tid = threadIdx.x;
    const int tx  = tid & 15;
    const int ty  = tid >> 4;

    for (int i = tid; i < 8192; i += 256) {
        int d = i >> 6, r = i & 63;
        float vw = 0.f, vh = 0.f;
        if (r < NREL) { vw = pew[d * NREL + r]; vh = peh[d * NREL + r]; }
        pw[i] = vw;
        ph[i] = vh;
    }

    const int gr0 = blockIdx.x * 64;   // global row = (b*4+h)*1024 + l
    for (int idx = tid; idx < 2048; idx += 256) {
        int i = idx >> 5, d4 = idx & 31;
        int gr = gr0 + i;
        int b = gr >> 12, h = (gr >> 10) & 3, l = gr & 1023;
        ((float4*)qs)[i * 33 + d4] =
            *(const float4*)&q[(size_t)((b << 10) + l) * 512 + (h << 7) + (d4 << 2)];
    }
    __syncthreads();

    float aw[4][4], ah[4][4];
#pragma unroll
    for (int i = 0; i < 4; i++)
#pragma unroll
        for (int j = 0; j < 4; j++) { aw[i][j] = 0.f; ah[i][j] = 0.f; }

#pragma unroll 4
    for (int d = 0; d < 128; d++) {
        float bw[4], bh[4], a[4];
        *(float4*)bw = *(const float4*)&pw[(d << 6) + tx * 4];
        *(float4*)bh = *(const float4*)&ph[(d << 6) + tx * 4];
#pragma unroll
        for (int i = 0; i < 4; i++) a[i] = qs[(ty * 4 + i) * 132 + d];
#pragma unroll
        for (int i = 0; i < 4; i++)
#pragma unroll
            for (int c = 0; c < 4; c++) {
                aw[i][c] += a[i] * bw[c];
                ah[i][c] += a[i] * bh[c];
            }
    }

#pragma unroll
    for (int i = 0; i < 4; i++) {
        int gr = gr0 + ty * 4 + i;
#pragma unroll
        for (int c = 0; c < 4; c++) {
            int r = tx * 4 + c;
            if (r < NREL) {
                rw[(size_t)gr * NREL + r] = aw[i][c];
                rh[(size_t)gr * NREL + r] = ah[i][c];
            }
        }
    }
}

// ---------------------------------------------------------------------------
// Flash attention with decomposed relative-position bias.
// CTA = (qt, h, b), BM=64 queries, BN=64 keys, 256 threads.
// Thread (ty,tx): rows ty*4..+3; QK cols {tx, tx+16, tx+32, tx+48};
// PV cols tx*8..+7.
// Dynamic smem: Qs/Ks/Vs [64][132] + Ss[64][65] + RWs/RHs[64][63] = 150,272 B.
// ---------------------------------------------------------------------------
#define Q_OFF   0
#define K_OFF   8448
#define V_OFF   16896
#define S_OFF   25344
#define RW_OFF  29504
#define RH_OFF  33536
#define ATTN_SMEM ((33536 + 4032) * 4)

__global__ __launch_bounds__(256) void attn(const float* __restrict__ q,
                                            const float* __restrict__ k,
                                            const float* __restrict__ v,
                                            const float* __restrict__ rw,
                                            const float* __restrict__ rh,
                                            float* __restrict__ aout)
{
    extern __shared__ float sm[];
    float* Qs  = sm + Q_OFF;
    float* Ks  = sm + K_OFF;
    float* Vs  = sm + V_OFF;
    float* Ss  = sm + S_OFF;
    float* RWs = sm + RW_OFF;
    float* RHs = sm + RH_OFF;

    const int tid = threadIdx.x;
    const int tx  = tid & 15;
    const int ty  = tid >> 4;
    const int qt  = blockIdx.x;
    const int h   = blockIdx.y;
    const int b   = blockIdx.z;
    const int qbase = qt * 64;

    // Load Q tile (64 x 128)
    const float* qg = q + (size_t)((b << 10) + qbase) * 512 + (h << 7);
    for (int idx = tid; idx < 2048; idx += 256) {
        int i = idx >> 5, d4 = idx & 31;
        ((float4*)Qs)[i * 33 + d4] = *(const float4*)&qg[(size_t)i * 512 + (d4 << 2)];
    }
    // Load RW/RH rows for this query tile (contiguous 64*63 floats)
    const float* RWg = rw + (size_t)(((b << 2) + h) * 1024 + qbase) * NREL;
    const float* RHg = rh + (size_t)(((b << 2) + h) * 1024 + qbase) * NREL;
    for (int i = tid; i < 64 * NREL; i += 256) { RWs[i] = RWg[i]; RHs[i] = RHg[i]; }

    float m_i[4], l_i[4], O[4][8];
    int yq[4], xq[4];
#pragma unroll
    for (int ii = 0; ii < 4; ii++) {
        m_i[ii] = -1e30f;
        l_i[ii] = 0.f;
        int lq = qbase + ty * 4 + ii;
        yq[ii] = lq >> 5;
        xq[ii] = lq & 31;
#pragma unroll
        for (int c = 0; c < 8; c++) O[ii][c] = 0.f;
    }

    for (int kt = 0; kt < 16; kt++) {
        const int kbase = kt * 64;
        __syncthreads();   // previous PV done reading Ss/Vs
        const float* kg = k + (size_t)((b << 10) + kbase) * 512 + (h << 7);
        const float* vg = v + (size_t)((b << 10) + kbase) * 512 + (h << 7);
        for (int idx = tid; idx < 2048; idx += 256) {
            int i = idx >> 5, d4 = idx & 31;
            ((float4*)Ks)[i * 33 + d4] = *(const float4*)&kg[(size_t)i * 512 + (d4 << 2)];
            ((float4*)Vs)[i * 33 + d4] = *(const float4*)&vg[(size_t)i * 512 + (d4 << 2)];
        }
        __syncthreads();

        // S = Q @ K^T (4x4 micro, j strided by 16)
        float s[4][4];
#pragma unroll
        for (int i = 0; i < 4; i++)
#pragma unroll
            for (int j = 0; j < 4; j++) s[i][j] = 0.f;

        const float4* Q4 = (const float4*)Qs;
        const float4* K4 = (const float4*)Ks;
#pragma unroll 4
        for (int d4 = 0; d4 < 32; d4++) {
            float a[4][4], bb[4][4];
#pragma unroll
            for (int i = 0; i < 4; i++)
                *(float4*)a[i] = Q4[(ty * 4 + i) * 33 + d4];
#pragma unroll
            for (int j = 0; j < 4; j++)
                *(float4*)bb[j] = K4[(tx + (j << 4)) * 33 + d4];
#pragma unroll
            for (int i = 0; i < 4; i++)
#pragma unroll
                for (int j = 0; j < 4; j++)
#pragma unroll
                    for (int c = 0; c < 4; c++) s[i][j] += a[i][c] * bb[j][c];
        }

        // bias + online softmax
#pragma unroll
        for (int ii = 0; ii < 4; ii++) {
            const float* rwrow = &RWs[(ty * 4 + ii) * NREL];
            const float* rhrow = &RHs[(ty * 4 + ii) * NREL];
            float mx = -1e30f;
#pragma unroll
            for (int jj = 0; jj < 4; jj++) {
                int lk = kbase + tx + (jj << 4);
                int yk = lk >> 5, xk = lk & 31;
                s[ii][jj] += rwrow[xk - xq[ii] + 31] + rhrow[yk - yq[ii] + 31];
                mx = fmaxf(mx, s[ii][jj]);
            }
            mx = fmaxf(mx, __shfl_xor_sync(0xffffffffu, mx, 8));
            mx = fmaxf(mx, __shfl_xor_sync(0xffffffffu, mx, 4));
            mx = fmaxf(mx, __shfl_xor_sync(0xffffffffu, mx, 2));
            mx = fmaxf(mx, __shfl_xor_sync(0xffffffffu, mx, 1));
            float mnew  = fmaxf(m_i[ii], mx);
            float alpha = __expf(m_i[ii] - mnew);
            float ps = 0.f;
#pragma unroll
            for (int jj = 0; jj < 4; jj++) {
                float p = __expf(s[ii][jj] - mnew);
                Ss[(ty * 4 + ii) * 65 + tx + (jj << 4)] = p;
                ps += p;
            }
            ps += __shfl_xor_sync(0xffffffffu, ps, 8);
            ps += __shfl_xor_sync(0xffffffffu, ps, 4);
            ps += __shfl_xor_sync(0xffffffffu, ps, 2);
            ps += __shfl_xor_sync(0xffffffffu, ps, 1);
            l_i[ii] = l_i[ii] * alpha + ps;
            m_i[ii] = mnew;
#pragma unroll
            for (int c = 0; c < 8; c++) O[ii][c] *= alpha;
        }
        __syncthreads();   // Ss fully written

        // O += P @ V
        const float4* V4 = (const float4*)Vs;
#pragma unroll 2
        for (int j = 0; j < 64; j++) {
            float vv[8];
            *(float4*)&vv[0] = V4[j * 33 + (tx << 1)];
            *(float4*)&vv[4] = V4[j * 33 + (tx << 1) + 1];
            float pp[4];
#pragma unroll
            for (int ii = 0; ii < 4; ii++) pp[ii] = Ss[(ty * 4 + ii) * 65 + j];
#pragma unroll
            for (int ii = 0; ii < 4; ii++)
#pragma unroll
                for (int c = 0; c < 8; c++) O[ii][c] += pp[ii] * vv[c];
        }
    }

    // normalize + store [B, L, heads*kd]
    float* og = aout + (size_t)((b << 10) + qbase) * 512 + (h << 7);
#pragma unroll
    for (int ii = 0; ii < 4; ii++) {
        float inv = 1.0f / l_i[ii];
        float4 o0 = make_float4(O[ii][0]*inv, O[ii][1]*inv, O[ii][2]*inv, O[ii][3]*inv);
        float4 o1 = make_float4(O[ii][4]*inv, O[ii][5]*inv, O[ii][6]*inv, O[ii][7]*inv);
        size_t base = (size_t)(ty * 4 + ii) * 512 + (tx << 3);
        *(float4*)&og[base]     = o0;
        *(float4*)&og[base + 4] = o1;
    }
}

// ---------------------------------------------------------------------------
extern "C" void kernel_launch(void* const* d_in, const int* in_sizes, int n_in,
                              void* d_out, int out_size)
{
    const float* x   = (const float*)d_in[0];
    const float* Wq  = (const float*)d_in[1];
    const float* Wk  = (const float*)d_in[2];
    const float* Wv  = (const float*)d_in[3];
    const float* Wo  = (const float*)d_in[4];
    const float* pew = (const float*)d_in[5];
    const float* peh = (const float*)d_in[6];
    float* out = (float*)d_out;

    float *qp, *kp, *vp, *aop, *rwp, *rhp;
    cudaGetSymbolAddress((void**)&qp,  g_q);
    cudaGetSymbolAddress((void**)&kp,  g_k);
    cudaGetSymbolAddress((void**)&vp,  g_v);
    cudaGetSymbolAddress((void**)&aop, g_ao);
    cudaGetSymbolAddress((void**)&rwp, g_rw);
    cudaGetSymbolAddress((void**)&rhp, g_rh);

    cudaFuncSetAttribute(relpos, cudaFuncAttributeMaxDynamicSharedMemorySize, RELPOS_SMEM);
    cudaFuncSetAttribute(attn,   cudaFuncAttributeMaxDynamicSharedMemorySize, ATTN_SMEM);

    const float scale = 0.08838834764831845f;   // 1/sqrt(128)
    dim3 gg(4, 64);
    gemm512<<<gg, 256>>>(x, Wq, qp, scale);
    gemm512<<<gg, 256>>>(x, Wk, kp, 1.0f);
    gemm512<<<gg, 256>>>(x, Wv, vp, 1.0f);
    relpos<<<512, 256, RELPOS_SMEM>>>(qp, pew, peh, rwp, rhp);
    attn<<<dim3(16, 4, 8), 256, ATTN_SMEM>>>(qp, kp, vp, rwp, rhp, aop);
    gemm512<<<gg, 256>>>(aop, Wo, out, 1.0f);
}